// round 8
// baseline (speedup 1.0000x reference)
#include <cuda_runtime.h>
#include <cuda_fp16.h>

// SConv R6: R5 pipeline with 512-thread CTAs (16 warps, 4Mx4N, warp 32x64)
// for 2x issue/occupancy. mma.sync m16n8k16 fp16, cp.async 3-stage pipeline,
// all shifts pre-applied in global memory.

#define B_  16
#define C1  128
#define C2  256
#define H_  128
#define W_  128
#define HW  (H_*W_)
#define EPSBN 1e-5f

typedef unsigned int uint;

#define XVSZ ((size_t)B_ * C1 * HW)

__device__ __half g_xv [3 * XVSZ];                // x fp16, col-shift variants -1/0/+1
__device__ __half g_yi [(size_t)B_ * C2 * HW];    // y fp16 plain (identity)
__device__ __half g_ysh[(size_t)B_ * C2 * HW];    // y fp16 pre-shifted per group
__device__ __half g_wA16[36 * 2 * 4096];          // conv w, frag order
__device__ __half g_wB16[ 8 * 2 * 4096];          // 1x1 w, frag order

__device__ __forceinline__ float silu_f(float v) { return v / (1.0f + __expf(-v)); }
__device__ __forceinline__ uint smem_u32(const void* p) {
    uint a;
    asm("{ .reg .u64 t; cvta.to.shared.u64 t, %1; cvt.u32.u64 %0, t; }" : "=r"(a) : "l"(p));
    return a;
}

#define MMA16(d, a, b0v, b1v) \
    asm volatile("mma.sync.aligned.m16n8k16.row.col.f32.f16.f16.f32 " \
        "{%0,%1,%2,%3}, {%4,%5,%6,%7}, {%8,%9}, {%0,%1,%2,%3};" \
        : "+f"((d)[0]), "+f"((d)[1]), "+f"((d)[2]), "+f"((d)[3]) \
        : "r"((a).x), "r"((a).y), "r"((a).z), "r"((a).w), "r"(b0v), "r"(b1v))

#define CP_A16(sm, gp) \
    asm volatile("cp.async.cg.shared.global [%0], [%1], 16;" :: "r"(sm), "l"(gp))
#define CP_A16Z(sm, gp, sz) \
    asm volatile("cp.async.cg.shared.global [%0], [%1], 16, %2;" :: "r"(sm), "l"(gp), "r"(sz))
#define CP_COMMIT() asm volatile("cp.async.commit_group;")
#define CP_WAIT1()  asm volatile("cp.async.wait_group 1;" ::: "memory")
#define CP_WAIT0()  asm volatile("cp.async.wait_group 0;" ::: "memory")

// Stage: A 8192 B (frag order) + B 16384 B (row-major [kk][n], 512B rows,
// 16B-granule XOR swizzle: granule (kk,g) at kk*512 + ((g^(kk&7))<<4)).
#define A_BYTES 8192
#define B_BYTES 16384
#define STAGE   (A_BYTES + B_BYTES)
#define NSTG    3
#define DSMEM_BYTES (NSTG * STAGE)   // 73728

#define NTHR 512

// --------------------------------------------------------- repack kernels --
__device__ __forceinline__ int fragoff(int m, int kk) {
    return (((kk >> 4) * 8 + (m >> 4)) * 32 + (((m & 7) << 2) | ((kk >> 1) & 3))) * 8
         + (((kk >> 3) & 1) * 2 + ((m >> 3) & 1)) * 2 + (kk & 1);
}
__global__ __launch_bounds__(256) void k_repack_conv(const float* __restrict__ wc) {
    int idx = blockIdx.x * 256 + threadIdx.x;
    if (idx >= C2 * C1 * 9) return;
    int tap = idx % 9, rest = idx / 9;
    int ic = rest % C1, oc = rest / C1;
    int it = (ic >> 5) * 9 + tap;
    g_wA16[(size_t)(it * 2 + (oc >> 7)) * 4096 + fragoff(oc & 127, ic & 31)] =
        __float2half_rn(wc[idx]);
}
__global__ __launch_bounds__(256) void k_repack_pw(const float* __restrict__ w1) {
    int idx = blockIdx.x * 256 + threadIdx.x;
    if (idx >= C2 * C2) return;
    int ic = idx % C2, oc = idx / C2;
    g_wB16[(size_t)((ic >> 5) * 2 + (oc >> 7)) * 4096 + fragoff(oc & 127, ic & 31)] =
        __float2half_rn(w1[idx]);
}

__global__ __launch_bounds__(256) void k_prep_x(const float* __restrict__ x) {
    size_t i = (size_t)blockIdx.x * 256 + threadIdx.x;   // over XVSZ/8
    size_t base = i * 8;
    int w0 = (int)(base & 127);
    const float* p = x + base;
    float4 a  = __ldg((const float4*)p);
    float4 b4 = __ldg((const float4*)(p + 4));
    float xm1 = (w0 > 0)   ? __ldg(p - 1) : 0.f;
    float xp8 = (w0 < 120) ? __ldg(p + 8) : 0.f;
    __half2* v0 = (__half2*)g_xv + i * 4;
    __half2* v1 = (__half2*)(g_xv + XVSZ) + i * 4;
    __half2* v2 = (__half2*)(g_xv + 2 * XVSZ) + i * 4;
    v1[0] = __floats2half2_rn(a.x, a.y);  v1[1] = __floats2half2_rn(a.z, a.w);
    v1[2] = __floats2half2_rn(b4.x, b4.y); v1[3] = __floats2half2_rn(b4.z, b4.w);
    v0[0] = __floats2half2_rn(xm1, a.x);  v0[1] = __floats2half2_rn(a.y, a.z);
    v0[2] = __floats2half2_rn(a.w, b4.x); v0[3] = __floats2half2_rn(b4.y, b4.z);
    v2[0] = __floats2half2_rn(a.y, a.z);  v2[1] = __floats2half2_rn(a.w, b4.x);
    v2[2] = __floats2half2_rn(b4.y, b4.z); v2[3] = __floats2half2_rn(b4.w, xp8);
}

__global__ __launch_bounds__(256) void k_zero_sh() {
    int idx = blockIdx.x * 256 + threadIdx.x;   // 524288
    if (idx >= 4 * 16 * 64 * 128) return;
    int grp = idx >> 17, r = idx & 131071;
    int b = r >> 13, r2 = r & 8191;
    int c = r2 >> 7, p = r2 & 127;
    int oc, h, w;
    if      (grp == 0) { oc = c;       h = p;   w = 0;   }
    else if (grp == 1) { oc = 64 + c;  h = 127; w = p;   }
    else if (grp == 2) { oc = 128 + c; h = p;   w = 127; }
    else               { oc = 192 + c; h = 0;   w = p;   }
    g_ysh[(((size_t)b * C2 + oc) << 14) + h * W_ + w] = __float2half_rn(0.f);
}

// --------------------------------------------------------- staging helpers --
__device__ __forceinline__ void cp_issue_A(uint Asm, const __half* src, int tid) {
    CP_A16(Asm + tid * 16, (const char*)src + tid * 16);
}
// B: thread owns granule column g (=tid&31), rows kk0 and kk0+16 (kk0=tid>>5 &15).
__device__ __forceinline__ void cp_issue_B(uint Bsm, const __half* vbase,
                                           int kk0, uint gxor, int hs, int wcol) {
    uint ok = ((uint)hs < 128u) ? 16u : 0u;
    int hsc = (hs < 0) ? 0 : (hs > 127 ? 127 : hs);
    const char* s = (const char*)(vbase + (size_t)kk0 * HW + hsc * W_ + wcol);
    uint d = Bsm + kk0 * 512 + gxor;      // (kk0+16)&7 == kk0&7 -> same gxor
    CP_A16Z(d, s, ok);
    CP_A16Z(d + 16 * 512, s + (size_t)16 * HW * 2, ok);
}

// ----------------------------------------------------------------- MMA -----
// warp tile 32x64: wm=wrp>>2 (0..3), wn=wrp&3. mf in 0..1.
__device__ __forceinline__ void mma_chunk(uint Asm, uint Bsm, int wm, int wn,
                                          int lane, float acc[2][8][4]) {
    const int j = lane >> 3, r = lane & 7;
    const int jk = (j & 1) << 3, jn = j >> 1;
#pragma unroll
    for (int ks = 0; ks < 2; ++ks) {
        uint4 a[2];
#pragma unroll
        for (int mf = 0; mf < 2; ++mf) {
            uint ad = Asm + (((ks * 8 + wm * 2 + mf) * 32 + lane) << 4);
            asm volatile("ld.shared.v4.b32 {%0,%1,%2,%3}, [%4];"
                : "=r"(a[mf].x), "=r"(a[mf].y), "=r"(a[mf].z), "=r"(a[mf].w) : "r"(ad));
        }
        uint bf[8][2];
#pragma unroll
        for (int p = 0; p < 4; ++p) {
            int krow = ks * 16 + jk + r;
            int oct  = wn * 8 + 2 * p + jn;
            uint ad = Bsm + krow * 512 + ((uint)(oct ^ (krow & 7)) << 4);
            uint d0, d1, d2, d3;
            asm volatile("ldmatrix.sync.aligned.m8n8.x4.trans.shared.b16 "
                "{%0,%1,%2,%3}, [%4];"
                : "=r"(d0), "=r"(d1), "=r"(d2), "=r"(d3) : "r"(ad));
            bf[2 * p][0] = d0; bf[2 * p][1] = d1;
            bf[2 * p + 1][0] = d2; bf[2 * p + 1][1] = d3;
        }
#pragma unroll
        for (int mf = 0; mf < 2; ++mf)
#pragma unroll
            for (int nf = 0; nf < 8; ++nf)
                MMA16(acc[mf][nf], a[mf], bf[nf][0], bf[nf][1]);
    }
}

// ------------------------------------------------------ conv3x3 + BN + SiLU
__global__ __launch_bounds__(NTHR, 1) void k_conv3(
    const float* __restrict__ gamma, const float* __restrict__ beta,
    const float* __restrict__ mean,  const float* __restrict__ var)
{
    extern __shared__ __align__(16) char dsm[];
    const uint smb = smem_u32(dsm);

    const int tid = threadIdx.x;
    const int wrp = tid >> 5, lane = tid & 31;
    const int wm = wrp >> 2, wn = wrp & 3;
    const int kk0 = (tid >> 5) & 15, g = tid & 31;
    const int rowsel = g >> 4, wcol = (g & 15) * 8;
    const uint gxor = ((uint)(g ^ (kk0 & 7))) << 4;
    const int h0  = blockIdx.x * 2;
    const int ocg = blockIdx.y, oc0 = ocg * 128;
    const int b   = blockIdx.z;

    float acc[2][8][4];
#pragma unroll
    for (int i = 0; i < 2; ++i)
#pragma unroll
        for (int jj = 0; jj < 8; ++jj)
#pragma unroll
            for (int q = 0; q < 4; ++q) acc[i][jj][q] = 0.0f;

    const size_t bofs = (size_t)b * C1 * HW;
#define ISSUE_CONV(nit, s) do { \
        int kc_ = (nit) / 9, tap_ = (nit) - 9 * kc_; \
        int ky_ = tap_ / 3, kx_ = tap_ - 3 * ky_; \
        cp_issue_A(smb + (s) * STAGE, g_wA16 + (size_t)((nit) * 2 + ocg) * 4096, tid); \
        const __half* vb_ = g_xv + (size_t)kx_ * XVSZ + bofs + (size_t)kc_ * 32 * HW; \
        cp_issue_B(smb + (s) * STAGE + A_BYTES, vb_, kk0, gxor, h0 + rowsel + ky_ - 1, wcol); \
        CP_COMMIT(); \
    } while (0)

    ISSUE_CONV(0, 0);
    ISSUE_CONV(1, 1);

#pragma unroll 1
    for (int it = 0; it < 36; ++it) {
        if (it + 2 < 36) CP_WAIT1(); else CP_WAIT0();
        __syncthreads();
        if (it + 2 < 36) {
            int s = (it + 2) % NSTG;
            ISSUE_CONV(it + 2, s);
        }
        int cs = it % NSTG;
        mma_chunk(smb + cs * STAGE, smb + cs * STAGE + A_BYTES, wm, wn, lane, acc);
    }
#undef ISSUE_CONV

    // epilogue: BN + SiLU -> g_yi (plain) + g_ysh (shifted by group)
    const int grp = ((oc0 + wm * 32) >> 6) & 3;   // warp-uniform
#pragma unroll
    for (int mf = 0; mf < 2; ++mf) {
        const int oc_a = oc0 + wm * 32 + mf * 16 + (lane >> 2);
        const int oc_b = oc_a + 8;
        const float inva = __ldg(&gamma[oc_a]) * rsqrtf(__ldg(&var[oc_a]) + EPSBN);
        const float bba  = __ldg(&beta[oc_a]) - __ldg(&mean[oc_a]) * inva;
        const float invb = __ldg(&gamma[oc_b]) * rsqrtf(__ldg(&var[oc_b]) + EPSBN);
        const float bbb  = __ldg(&beta[oc_b]) - __ldg(&mean[oc_b]) * invb;
        const size_t ra = ((size_t)b * C2 + oc_a) * HW;
        const size_t rb = ((size_t)b * C2 + oc_b) * HW;
#pragma unroll
        for (int nf = 0; nf < 8; ++nf) {
            const int n = wn * 64 + nf * 8 + (lane & 3) * 2;
            const int h = h0 + (n >> 7), w = n & 127;
            const int off = h * W_ + w;
            float2 u, v;
            u.x = silu_f(acc[mf][nf][0] * inva + bba);
            u.y = silu_f(acc[mf][nf][1] * inva + bba);
            v.x = silu_f(acc[mf][nf][2] * invb + bbb);
            v.y = silu_f(acc[mf][nf][3] * invb + bbb);
            __half2 uh = __floats2half2_rn(u.x, u.y);
            __half2 vh = __floats2half2_rn(v.x, v.y);
            *(__half2*)(g_yi + ra + off) = uh;
            *(__half2*)(g_yi + rb + off) = vh;
            if (grp == 0) {            // dest (h, w+1)
                g_ysh[ra + off + 1] = __low2half(uh);
                g_ysh[rb + off + 1] = __low2half(vh);
                if (w < 126) {
                    g_ysh[ra + off + 2] = __high2half(uh);
                    g_ysh[rb + off + 2] = __high2half(vh);
                }
            } else if (grp == 1) {     // dest (h-1, w)
                if (h > 0) {
                    *(__half2*)(g_ysh + ra + off - W_) = uh;
                    *(__half2*)(g_ysh + rb + off - W_) = vh;
                }
            } else if (grp == 2) {     // dest (h, w-1)
                if (w > 0) {
                    g_ysh[ra + off - 1] = __low2half(uh);
                    g_ysh[rb + off - 1] = __low2half(vh);
                }
                g_ysh[ra + off] = __high2half(uh);
                g_ysh[rb + off] = __high2half(vh);
            } else {                   // dest (h+1, w)
                if (h < 127) {
                    *(__half2*)(g_ysh + ra + off + W_) = uh;
                    *(__half2*)(g_ysh + rb + off + W_) = vh;
                }
            }
        }
    }
}

// --------------------------- conv1x1(shifted y) + bias + BN + id + SiLU ----
__global__ __launch_bounds__(NTHR, 1) void k_pw(
    const float* __restrict__ b1,
    const float* __restrict__ gamma, const float* __restrict__ beta,
    const float* __restrict__ mean,  const float* __restrict__ var,
    float* __restrict__ out)
{
    extern __shared__ __align__(16) char dsm[];
    const uint smb = smem_u32(dsm);

    const int tid = threadIdx.x;
    const int wrp = tid >> 5, lane = tid & 31;
    const int wm = wrp >> 2, wn = wrp & 3;
    const int kk0 = (tid >> 5) & 15, g = tid & 31;
    const int rowsel = g >> 4, wcol = (g & 15) * 8;
    const uint gxor = ((uint)(g ^ (kk0 & 7))) << 4;
    const int h0  = blockIdx.x * 2;
    const int ocg = blockIdx.y, oc0 = ocg * 128;
    const int b   = blockIdx.z;

    float acc[2][8][4];
#pragma unroll
    for (int i = 0; i < 2; ++i)
#pragma unroll
        for (int jj = 0; jj < 8; ++jj)
#pragma unroll
            for (int q = 0; q < 4; ++q) acc[i][jj][q] = 0.0f;

    const size_t bofs = (size_t)b * C2 * HW;
#define ISSUE_PW(nit, s) do { \
        cp_issue_A(smb + (s) * STAGE, g_wB16 + (size_t)((nit) * 2 + ocg) * 4096, tid); \
        const __half* vb_ = g_ysh + bofs + (size_t)(nit) * 32 * HW; \
        cp_issue_B(smb + (s) * STAGE + A_BYTES, vb_, kk0, gxor, h0 + rowsel, wcol); \
        CP_COMMIT(); \
    } while (0)

    ISSUE_PW(0, 0);
    ISSUE_PW(1, 1);

#pragma unroll 1
    for (int it = 0; it < 8; ++it) {
        if (it + 2 < 8) CP_WAIT1(); else CP_WAIT0();
        __syncthreads();
        if (it + 2 < 8) {
            int s = (it + 2) % NSTG;
            ISSUE_PW(it + 2, s);
        }
        int cs = it % NSTG;
        mma_chunk(smb + cs * STAGE, smb + cs * STAGE + A_BYTES, wm, wn, lane, acc);
    }
#undef ISSUE_PW

    // epilogue: +bias, BN, +identity(fp16), SiLU -> out (fp32)
#pragma unroll
    for (int mf = 0; mf < 2; ++mf) {
        const int oc_a = oc0 + wm * 32 + mf * 16 + (lane >> 2);
        const int oc_b = oc_a + 8;
        const float inva = __ldg(&gamma[oc_a]) * rsqrtf(__ldg(&var[oc_a]) + EPSBN);
        const float bba  = __ldg(&beta[oc_a]) - __ldg(&mean[oc_a]) * inva;
        const float bsa  = __ldg(&b1[oc_a]);
        const float invb = __ldg(&gamma[oc_b]) * rsqrtf(__ldg(&var[oc_b]) + EPSBN);
        const float bbb  = __ldg(&beta[oc_b]) - __ldg(&mean[oc_b]) * invb;
        const float bsb  = __ldg(&b1[oc_b]);
        const size_t ra = ((size_t)b * C2 + oc_a) * HW;
        const size_t rb = ((size_t)b * C2 + oc_b) * HW;
#pragma unroll
        for (int nf = 0; nf < 8; ++nf) {
            const int n = wn * 64 + nf * 8 + (lane & 3) * 2;
            const int off = (h0 + (n >> 7)) * W_ + (n & 127);
            float2 ida = __half22float2(*(const __half2*)(g_yi + ra + off));
            float2 idb = __half22float2(*(const __half2*)(g_yi + rb + off));
            float2 u, v; float z;
            z = (acc[mf][nf][0] + bsa) * inva + bba + ida.x; u.x = silu_f(z);
            z = (acc[mf][nf][1] + bsa) * inva + bba + ida.y; u.y = silu_f(z);
            z = (acc[mf][nf][2] + bsb) * invb + bbb + idb.x; v.x = silu_f(z);
            z = (acc[mf][nf][3] + bsb) * invb + bbb + idb.y; v.y = silu_f(z);
            *(float2*)(out + ra + off) = u;
            *(float2*)(out + rb + off) = v;
        }
    }
}

// ---------------------------------------------------------------------------
extern "C" void kernel_launch(void* const* d_in, const int* in_sizes, int n_in,
                              void* d_out, int out_size)
{
    const float* x     = (const float*)d_in[0];
    const float* wconv = (const float*)d_in[1];
    const float* w1    = (const float*)d_in[2];
    const float* b1    = (const float*)d_in[3];
    const float* gamma = (const float*)d_in[4];
    const float* beta  = (const float*)d_in[5];
    const float* mean  = (const float*)d_in[6];
    const float* var   = (const float*)d_in[7];
    float* out = (float*)d_out;

    static bool attr_done = false;
    if (!attr_done) {
        cudaFuncSetAttribute(k_conv3, cudaFuncAttributeMaxDynamicSharedMemorySize, DSMEM_BYTES);
        cudaFuncSetAttribute(k_pw,    cudaFuncAttributeMaxDynamicSharedMemorySize, DSMEM_BYTES);
        attr_done = true;
    }

    k_repack_conv<<<(C2 * C1 * 9 + 255) / 256, 256>>>(wconv);
    k_repack_pw  <<<(C2 * C2 + 255) / 256, 256>>>(w1);
    k_prep_x     <<<(int)(XVSZ / 8 / 256), 256>>>(x);
    k_zero_sh    <<<(4 * 16 * 64 * 128 + 255) / 256, 256>>>();

    dim3 grid(H_ / 2, 2, B_);
    k_conv3<<<grid, NTHR, DSMEM_BYTES>>>(gamma, beta, mean, var);
    k_pw   <<<grid, NTHR, DSMEM_BYTES>>>(b1, gamma, beta, mean, var, out);
}

// round 9
// speedup vs baseline: 1.2355x; 1.2355x over previous
#include <cuda_runtime.h>
#include <cuda_fp16.h>

// SConv R8: R6 pipeline resized for 2 CTAs/SM.
// CTA: 256 thr (8 warps, 4Mx2N), tile 128oc x 128px (one row), warp 32x64.
// mma.sync m16n8k16 fp16, cp.async 3-stage pipeline, shifts pre-applied in gmem.

#define B_  16
#define C1  128
#define C2  256
#define H_  128
#define W_  128
#define HW  (H_*W_)
#define EPSBN 1e-5f

typedef unsigned int uint;

#define XVSZ ((size_t)B_ * C1 * HW)

__device__ __half g_xv [3 * XVSZ];                // x fp16, col-shift variants -1/0/+1
__device__ __half g_yi [(size_t)B_ * C2 * HW];    // y fp16 plain (identity)
__device__ __half g_ysh[(size_t)B_ * C2 * HW];    // y fp16 pre-shifted per group
__device__ __half g_wA16[36 * 2 * 4096];          // conv w, frag order
__device__ __half g_wB16[ 8 * 2 * 4096];          // 1x1 w, frag order

__device__ __forceinline__ float silu_f(float v) { return v / (1.0f + __expf(-v)); }
__device__ __forceinline__ uint smem_u32(const void* p) {
    uint a;
    asm("{ .reg .u64 t; cvta.to.shared.u64 t, %1; cvt.u32.u64 %0, t; }" : "=r"(a) : "l"(p));
    return a;
}

#define MMA16(d, a, b0v, b1v) \
    asm volatile("mma.sync.aligned.m16n8k16.row.col.f32.f16.f16.f32 " \
        "{%0,%1,%2,%3}, {%4,%5,%6,%7}, {%8,%9}, {%0,%1,%2,%3};" \
        : "+f"((d)[0]), "+f"((d)[1]), "+f"((d)[2]), "+f"((d)[3]) \
        : "r"((a).x), "r"((a).y), "r"((a).z), "r"((a).w), "r"(b0v), "r"(b1v))

#define CP_A16(sm, gp) \
    asm volatile("cp.async.cg.shared.global [%0], [%1], 16;" :: "r"(sm), "l"(gp))
#define CP_A16Z(sm, gp, sz) \
    asm volatile("cp.async.cg.shared.global [%0], [%1], 16, %2;" :: "r"(sm), "l"(gp), "r"(sz))
#define CP_COMMIT() asm volatile("cp.async.commit_group;")
#define CP_WAIT1()  asm volatile("cp.async.wait_group 1;" ::: "memory")
#define CP_WAIT0()  asm volatile("cp.async.wait_group 0;" ::: "memory")

// Stage: A 8192 B (frag order) + B 8192 B (row-major [kk 32][n 128], 256B rows,
// 16B-granule XOR swizzle: granule (kk,g) at kk*256 + ((g^(kk&7))<<4)).
#define A_BYTES 8192
#define B_BYTES 8192
#define STAGE   (A_BYTES + B_BYTES)
#define NSTG    3
#define DSMEM_BYTES (NSTG * STAGE)   // 49152 per CTA, 2 CTAs/SM

#define NTHR 256

// --------------------------------------------------------- repack kernels --
__device__ __forceinline__ int fragoff(int m, int kk) {
    return (((kk >> 4) * 8 + (m >> 4)) * 32 + (((m & 7) << 2) | ((kk >> 1) & 3))) * 8
         + (((kk >> 3) & 1) * 2 + ((m >> 3) & 1)) * 2 + (kk & 1);
}
__global__ __launch_bounds__(256) void k_repack_conv(const float* __restrict__ wc) {
    int idx = blockIdx.x * 256 + threadIdx.x;
    if (idx >= C2 * C1 * 9) return;
    int tap = idx % 9, rest = idx / 9;
    int ic = rest % C1, oc = rest / C1;
    int it = (ic >> 5) * 9 + tap;
    g_wA16[(size_t)(it * 2 + (oc >> 7)) * 4096 + fragoff(oc & 127, ic & 31)] =
        __float2half_rn(wc[idx]);
}
__global__ __launch_bounds__(256) void k_repack_pw(const float* __restrict__ w1) {
    int idx = blockIdx.x * 256 + threadIdx.x;
    if (idx >= C2 * C2) return;
    int ic = idx % C2, oc = idx / C2;
    g_wB16[(size_t)((ic >> 5) * 2 + (oc >> 7)) * 4096 + fragoff(oc & 127, ic & 31)] =
        __float2half_rn(w1[idx]);
}

__global__ __launch_bounds__(256) void k_prep_x(const float* __restrict__ x) {
    size_t i = (size_t)blockIdx.x * 256 + threadIdx.x;   // over XVSZ/8
    size_t base = i * 8;
    int w0 = (int)(base & 127);
    const float* p = x + base;
    float4 a  = __ldg((const float4*)p);
    float4 b4 = __ldg((const float4*)(p + 4));
    float xm1 = (w0 > 0)   ? __ldg(p - 1) : 0.f;
    float xp8 = (w0 < 120) ? __ldg(p + 8) : 0.f;
    __half2* v0 = (__half2*)g_xv + i * 4;
    __half2* v1 = (__half2*)(g_xv + XVSZ) + i * 4;
    __half2* v2 = (__half2*)(g_xv + 2 * XVSZ) + i * 4;
    v1[0] = __floats2half2_rn(a.x, a.y);  v1[1] = __floats2half2_rn(a.z, a.w);
    v1[2] = __floats2half2_rn(b4.x, b4.y); v1[3] = __floats2half2_rn(b4.z, b4.w);
    v0[0] = __floats2half2_rn(xm1, a.x);  v0[1] = __floats2half2_rn(a.y, a.z);
    v0[2] = __floats2half2_rn(a.w, b4.x); v0[3] = __floats2half2_rn(b4.y, b4.z);
    v2[0] = __floats2half2_rn(a.y, a.z);  v2[1] = __floats2half2_rn(a.w, b4.x);
    v2[2] = __floats2half2_rn(b4.y, b4.z); v2[3] = __floats2half2_rn(b4.w, xp8);
}

__global__ __launch_bounds__(256) void k_zero_sh() {
    int idx = blockIdx.x * 256 + threadIdx.x;   // 524288
    if (idx >= 4 * 16 * 64 * 128) return;
    int grp = idx >> 17, r = idx & 131071;
    int b = r >> 13, r2 = r & 8191;
    int c = r2 >> 7, p = r2 & 127;
    int oc, h, w;
    if      (grp == 0) { oc = c;       h = p;   w = 0;   }
    else if (grp == 1) { oc = 64 + c;  h = 127; w = p;   }
    else if (grp == 2) { oc = 128 + c; h = p;   w = 127; }
    else               { oc = 192 + c; h = 0;   w = p;   }
    g_ysh[(((size_t)b * C2 + oc) << 14) + h * W_ + w] = __float2half_rn(0.f);
}

// --------------------------------------------------------- staging helpers --
__device__ __forceinline__ void cp_issue_A(uint Asm, const __half* src, int tid) {
    CP_A16(Asm + tid * 16, (const char*)src + tid * 16);
    CP_A16(Asm + 4096 + tid * 16, (const char*)src + 4096 + tid * 16);
}
// B: thread owns granule column g (=tid&15), rows kk0 and kk0+16 (kk0=tid>>4).
__device__ __forceinline__ void cp_issue_B(uint Bsm, const __half* vbase,
                                           int kk0, uint gxor, int hs, int wcol) {
    uint ok = ((uint)hs < 128u) ? 16u : 0u;
    int hsc = (hs < 0) ? 0 : (hs > 127 ? 127 : hs);
    const char* s = (const char*)(vbase + (size_t)kk0 * HW + hsc * W_ + wcol);
    uint d = Bsm + kk0 * 256 + gxor;      // (kk0+16)&7 == kk0&7 -> same gxor
    CP_A16Z(d, s, ok);
    CP_A16Z(d + 16 * 256, s + (size_t)16 * HW * 2, ok);
}

// ----------------------------------------------------------------- MMA -----
// warp tile 32oc x 64px: wm=wrp>>1 (0..3), wn=wrp&1 (0..1). mf in 0..1, nf 0..7.
__device__ __forceinline__ void mma_chunk(uint Asm, uint Bsm, int wm, int wn,
                                          int lane, float acc[2][8][4]) {
    const int j = lane >> 3, r = lane & 7;
    const int jk = (j & 1) << 3, jn = j >> 1;
#pragma unroll
    for (int ks = 0; ks < 2; ++ks) {
        uint4 a[2];
#pragma unroll
        for (int mf = 0; mf < 2; ++mf) {
            uint ad = Asm + (((ks * 8 + wm * 2 + mf) * 32 + lane) << 4);
            asm volatile("ld.shared.v4.b32 {%0,%1,%2,%3}, [%4];"
                : "=r"(a[mf].x), "=r"(a[mf].y), "=r"(a[mf].z), "=r"(a[mf].w) : "r"(ad));
        }
        uint bf[8][2];
#pragma unroll
        for (int p = 0; p < 4; ++p) {
            int krow = ks * 16 + jk + r;
            int oct  = wn * 8 + 2 * p + jn;
            uint ad = Bsm + krow * 256 + ((uint)(oct ^ (krow & 7)) << 4);
            uint d0, d1, d2, d3;
            asm volatile("ldmatrix.sync.aligned.m8n8.x4.trans.shared.b16 "
                "{%0,%1,%2,%3}, [%4];"
                : "=r"(d0), "=r"(d1), "=r"(d2), "=r"(d3) : "r"(ad));
            bf[2 * p][0] = d0; bf[2 * p][1] = d1;
            bf[2 * p + 1][0] = d2; bf[2 * p + 1][1] = d3;
        }
#pragma unroll
        for (int mf = 0; mf < 2; ++mf)
#pragma unroll
            for (int nf = 0; nf < 8; ++nf)
                MMA16(acc[mf][nf], a[mf], bf[nf][0], bf[nf][1]);
    }
}

// ------------------------------------------------------ conv3x3 + BN + SiLU
__global__ __launch_bounds__(NTHR, 2) void k_conv3(
    const float* __restrict__ gamma, const float* __restrict__ beta,
    const float* __restrict__ mean,  const float* __restrict__ var)
{
    extern __shared__ __align__(16) char dsm[];
    const uint smb = smem_u32(dsm);

    const int tid = threadIdx.x;
    const int wrp = tid >> 5, lane = tid & 31;
    const int wm = wrp >> 1, wn = wrp & 1;
    const int kk0 = tid >> 4, g = tid & 15;
    const int wcol = g * 8;
    const uint gxor = ((uint)(g ^ (kk0 & 7))) << 4;
    const int h0  = blockIdx.x;
    const int ocg = blockIdx.y, oc0 = ocg * 128;
    const int b   = blockIdx.z;

    float acc[2][8][4];
#pragma unroll
    for (int i = 0; i < 2; ++i)
#pragma unroll
        for (int jj = 0; jj < 8; ++jj)
#pragma unroll
            for (int q = 0; q < 4; ++q) acc[i][jj][q] = 0.0f;

    const size_t bofs = (size_t)b * C1 * HW;
#define ISSUE_CONV(nit, s) do { \
        int kc_ = (nit) / 9, tap_ = (nit) - 9 * kc_; \
        int ky_ = tap_ / 3, kx_ = tap_ - 3 * ky_; \
        cp_issue_A(smb + (s) * STAGE, g_wA16 + (size_t)((nit) * 2 + ocg) * 4096, tid); \
        const __half* vb_ = g_xv + (size_t)kx_ * XVSZ + bofs + (size_t)kc_ * 32 * HW; \
        cp_issue_B(smb + (s) * STAGE + A_BYTES, vb_, kk0, gxor, h0 + ky_ - 1, wcol); \
        CP_COMMIT(); \
    } while (0)

    ISSUE_CONV(0, 0);
    ISSUE_CONV(1, 1);

#pragma unroll 1
    for (int it = 0; it < 36; ++it) {
        if (it + 2 < 36) CP_WAIT1(); else CP_WAIT0();
        __syncthreads();
        if (it + 2 < 36) {
            int s = (it + 2) % NSTG;
            ISSUE_CONV(it + 2, s);
        }
        int cs = it % NSTG;
        mma_chunk(smb + cs * STAGE, smb + cs * STAGE + A_BYTES, wm, wn, lane, acc);
    }
#undef ISSUE_CONV

    // epilogue: BN + SiLU -> g_yi (plain) + g_ysh (shifted by group)
    const int grp = ((oc0 + wm * 32) >> 6) & 3;   // warp-uniform
    const int h = h0;
#pragma unroll
    for (int mf = 0; mf < 2; ++mf) {
        const int oc_a = oc0 + wm * 32 + mf * 16 + (lane >> 2);
        const int oc_b = oc_a + 8;
        const float inva = __ldg(&gamma[oc_a]) * rsqrtf(__ldg(&var[oc_a]) + EPSBN);
        const float bba  = __ldg(&beta[oc_a]) - __ldg(&mean[oc_a]) * inva;
        const float invb = __ldg(&gamma[oc_b]) * rsqrtf(__ldg(&var[oc_b]) + EPSBN);
        const float bbb  = __ldg(&beta[oc_b]) - __ldg(&mean[oc_b]) * invb;
        const size_t ra = ((size_t)b * C2 + oc_a) * HW;
        const size_t rb = ((size_t)b * C2 + oc_b) * HW;
#pragma unroll
        for (int nf = 0; nf < 8; ++nf) {
            const int w = wn * 64 + nf * 8 + (lane & 3) * 2;
            const int off = h * W_ + w;
            float2 u, v;
            u.x = silu_f(acc[mf][nf][0] * inva + bba);
            u.y = silu_f(acc[mf][nf][1] * inva + bba);
            v.x = silu_f(acc[mf][nf][2] * invb + bbb);
            v.y = silu_f(acc[mf][nf][3] * invb + bbb);
            __half2 uh = __floats2half2_rn(u.x, u.y);
            __half2 vh = __floats2half2_rn(v.x, v.y);
            *(__half2*)(g_yi + ra + off) = uh;
            *(__half2*)(g_yi + rb + off) = vh;
            if (grp == 0) {            // dest (h, w+1)
                g_ysh[ra + off + 1] = __low2half(uh);
                g_ysh[rb + off + 1] = __low2half(vh);
                if (w < 126) {
                    g_ysh[ra + off + 2] = __high2half(uh);
                    g_ysh[rb + off + 2] = __high2half(vh);
                }
            } else if (grp == 1) {     // dest (h-1, w)
                if (h > 0) {
                    *(__half2*)(g_ysh + ra + off - W_) = uh;
                    *(__half2*)(g_ysh + rb + off - W_) = vh;
                }
            } else if (grp == 2) {     // dest (h, w-1)
                if (w > 0) {
                    g_ysh[ra + off - 1] = __low2half(uh);
                    g_ysh[rb + off - 1] = __low2half(vh);
                }
                g_ysh[ra + off] = __high2half(uh);
                g_ysh[rb + off] = __high2half(vh);
            } else {                   // dest (h+1, w)
                if (h < 127) {
                    *(__half2*)(g_ysh + ra + off + W_) = uh;
                    *(__half2*)(g_ysh + rb + off + W_) = vh;
                }
            }
        }
    }
}

// --------------------------- conv1x1(shifted y) + bias + BN + id + SiLU ----
__global__ __launch_bounds__(NTHR, 2) void k_pw(
    const float* __restrict__ b1,
    const float* __restrict__ gamma, const float* __restrict__ beta,
    const float* __restrict__ mean,  const float* __restrict__ var,
    float* __restrict__ out)
{
    extern __shared__ __align__(16) char dsm[];
    const uint smb = smem_u32(dsm);

    const int tid = threadIdx.x;
    const int wrp = tid >> 5, lane = tid & 31;
    const int wm = wrp >> 1, wn = wrp & 1;
    const int kk0 = tid >> 4, g = tid & 15;
    const int wcol = g * 8;
    const uint gxor = ((uint)(g ^ (kk0 & 7))) << 4;
    const int h0  = blockIdx.x;
    const int ocg = blockIdx.y, oc0 = ocg * 128;
    const int b   = blockIdx.z;

    float acc[2][8][4];
#pragma unroll
    for (int i = 0; i < 2; ++i)
#pragma unroll
        for (int jj = 0; jj < 8; ++jj)
#pragma unroll
            for (int q = 0; q < 4; ++q) acc[i][jj][q] = 0.0f;

    const size_t bofs = (size_t)b * C2 * HW;
#define ISSUE_PW(nit, s) do { \
        cp_issue_A(smb + (s) * STAGE, g_wB16 + (size_t)((nit) * 2 + ocg) * 4096, tid); \
        const __half* vb_ = g_ysh + bofs + (size_t)(nit) * 32 * HW; \
        cp_issue_B(smb + (s) * STAGE + A_BYTES, vb_, kk0, gxor, h0, wcol); \
        CP_COMMIT(); \
    } while (0)

    ISSUE_PW(0, 0);
    ISSUE_PW(1, 1);

#pragma unroll 1
    for (int it = 0; it < 8; ++it) {
        if (it + 2 < 8) CP_WAIT1(); else CP_WAIT0();
        __syncthreads();
        if (it + 2 < 8) {
            int s = (it + 2) % NSTG;
            ISSUE_PW(it + 2, s);
        }
        int cs = it % NSTG;
        mma_chunk(smb + cs * STAGE, smb + cs * STAGE + A_BYTES, wm, wn, lane, acc);
    }
#undef ISSUE_PW

    // epilogue: +bias, BN, +identity(fp16), SiLU -> out (fp32)
    const int h = h0;
#pragma unroll
    for (int mf = 0; mf < 2; ++mf) {
        const int oc_a = oc0 + wm * 32 + mf * 16 + (lane >> 2);
        const int oc_b = oc_a + 8;
        const float inva = __ldg(&gamma[oc_a]) * rsqrtf(__ldg(&var[oc_a]) + EPSBN);
        const float bba  = __ldg(&beta[oc_a]) - __ldg(&mean[oc_a]) * inva;
        const float bsa  = __ldg(&b1[oc_a]);
        const float invb = __ldg(&gamma[oc_b]) * rsqrtf(__ldg(&var[oc_b]) + EPSBN);
        const float bbb  = __ldg(&beta[oc_b]) - __ldg(&mean[oc_b]) * invb;
        const float bsb  = __ldg(&b1[oc_b]);
        const size_t ra = ((size_t)b * C2 + oc_a) * HW;
        const size_t rb = ((size_t)b * C2 + oc_b) * HW;
#pragma unroll
        for (int nf = 0; nf < 8; ++nf) {
            const int w = wn * 64 + nf * 8 + (lane & 3) * 2;
            const int off = h * W_ + w;
            float2 ida = __half22float2(*(const __half2*)(g_yi + ra + off));
            float2 idb = __half22float2(*(const __half2*)(g_yi + rb + off));
            float2 u, v; float z;
            z = (acc[mf][nf][0] + bsa) * inva + bba + ida.x; u.x = silu_f(z);
            z = (acc[mf][nf][1] + bsa) * inva + bba + ida.y; u.y = silu_f(z);
            z = (acc[mf][nf][2] + bsb) * invb + bbb + idb.x; v.x = silu_f(z);
            z = (acc[mf][nf][3] + bsb) * invb + bbb + idb.y; v.y = silu_f(z);
            *(float2*)(out + ra + off) = u;
            *(float2*)(out + rb + off) = v;
        }
    }
}

// ---------------------------------------------------------------------------
extern "C" void kernel_launch(void* const* d_in, const int* in_sizes, int n_in,
                              void* d_out, int out_size)
{
    const float* x     = (const float*)d_in[0];
    const float* wconv = (const float*)d_in[1];
    const float* w1    = (const float*)d_in[2];
    const float* b1    = (const float*)d_in[3];
    const float* gamma = (const float*)d_in[4];
    const float* beta  = (const float*)d_in[5];
    const float* mean  = (const float*)d_in[6];
    const float* var   = (const float*)d_in[7];
    float* out = (float*)d_out;

    static bool attr_done = false;
    if (!attr_done) {
        cudaFuncSetAttribute(k_conv3, cudaFuncAttributeMaxDynamicSharedMemorySize, DSMEM_BYTES);
        cudaFuncSetAttribute(k_pw,    cudaFuncAttributeMaxDynamicSharedMemorySize, DSMEM_BYTES);
        attr_done = true;
    }

    k_repack_conv<<<(C2 * C1 * 9 + 255) / 256, 256>>>(wconv);
    k_repack_pw  <<<(C2 * C2 + 255) / 256, 256>>>(w1);
    k_prep_x     <<<(int)(XVSZ / 8 / 256), 256>>>(x);
    k_zero_sh    <<<(4 * 16 * 64 * 128 + 255) / 256, 256>>>();

    dim3 grid(H_, 2, B_);   // 128 rows x 2 oc-halves x 16 batch = 4096 CTAs
    k_conv3<<<grid, NTHR, DSMEM_BYTES>>>(gamma, beta, mean, var);
    k_pw   <<<grid, NTHR, DSMEM_BYTES>>>(b1, gamma, beta, mean, var, out);
}

// round 10
// speedup vs baseline: 1.2423x; 1.0055x over previous
#include <cuda_runtime.h>
#include <cuda_fp16.h>

// SConv R9: R8 with K=64 pipeline stages (2 chunks per barrier).
// CTA: 256 thr (8 warps, 4Mx2N), tile 128oc x 128px, warp 32x64, 2 CTAs/SM.
// conv3x3: 18 stages x K=64; conv1x1: 4 stages x K=64. cp.async 3-stage ring.

#define B_  16
#define C1  128
#define C2  256
#define H_  128
#define W_  128
#define HW  (H_*W_)
#define EPSBN 1e-5f

typedef unsigned int uint;

#define XVSZ ((size_t)B_ * C1 * HW)

__device__ __half g_xv [3 * XVSZ];                // x fp16, col-shift variants -1/0/+1
__device__ __half g_yi [(size_t)B_ * C2 * HW];    // y fp16 plain (identity)
__device__ __half g_ysh[(size_t)B_ * C2 * HW];    // y fp16 pre-shifted per group
__device__ __half g_wA16[36 * 2 * 4096];          // conv w, frag order
__device__ __half g_wB16[ 8 * 2 * 4096];          // 1x1 w, frag order

__device__ __forceinline__ float silu_f(float v) { return v / (1.0f + __expf(-v)); }
__device__ __forceinline__ uint smem_u32(const void* p) {
    uint a;
    asm("{ .reg .u64 t; cvta.to.shared.u64 t, %1; cvt.u32.u64 %0, t; }" : "=r"(a) : "l"(p));
    return a;
}

#define MMA16(d, a, b0v, b1v) \
    asm volatile("mma.sync.aligned.m16n8k16.row.col.f32.f16.f16.f32 " \
        "{%0,%1,%2,%3}, {%4,%5,%6,%7}, {%8,%9}, {%0,%1,%2,%3};" \
        : "+f"((d)[0]), "+f"((d)[1]), "+f"((d)[2]), "+f"((d)[3]) \
        : "r"((a).x), "r"((a).y), "r"((a).z), "r"((a).w), "r"(b0v), "r"(b1v))

#define CP_A16(sm, gp) \
    asm volatile("cp.async.cg.shared.global [%0], [%1], 16;" :: "r"(sm), "l"(gp))
#define CP_A16Z(sm, gp, sz) \
    asm volatile("cp.async.cg.shared.global [%0], [%1], 16, %2;" :: "r"(sm), "l"(gp), "r"(sz))
#define CP_COMMIT() asm volatile("cp.async.commit_group;")
#define CP_WAIT1()  asm volatile("cp.async.wait_group 1;" ::: "memory")
#define CP_WAIT0()  asm volatile("cp.async.wait_group 0;" ::: "memory")

// Sub-chunk (K=32): A 8192 B (frag order) + B 8192 B (row-major [kk 32][n 128],
// 256B rows, 16B-granule XOR swizzle). Stage = 2 sub-chunks = 32 KB.
#define A_BYTES 8192
#define B_BYTES 8192
#define CHUNK   (A_BYTES + B_BYTES)   // 16384
#define STAGE   (2 * CHUNK)           // 32768
#define NSTG    3
#define DSMEM_BYTES (NSTG * STAGE)    // 98304 per CTA, 2 CTAs/SM

#define NTHR 256

// --------------------------------------------------------- repack kernels --
__device__ __forceinline__ int fragoff(int m, int kk) {
    return (((kk >> 4) * 8 + (m >> 4)) * 32 + (((m & 7) << 2) | ((kk >> 1) & 3))) * 8
         + (((kk >> 3) & 1) * 2 + ((m >> 3) & 1)) * 2 + (kk & 1);
}
__global__ __launch_bounds__(256) void k_repack_conv(const float* __restrict__ wc) {
    int idx = blockIdx.x * 256 + threadIdx.x;
    if (idx >= C2 * C1 * 9) return;
    int tap = idx % 9, rest = idx / 9;
    int ic = rest % C1, oc = rest / C1;
    int it = (ic >> 5) * 9 + tap;
    g_wA16[(size_t)(it * 2 + (oc >> 7)) * 4096 + fragoff(oc & 127, ic & 31)] =
        __float2half_rn(wc[idx]);
}
__global__ __launch_bounds__(256) void k_repack_pw(const float* __restrict__ w1) {
    int idx = blockIdx.x * 256 + threadIdx.x;
    if (idx >= C2 * C2) return;
    int ic = idx % C2, oc = idx / C2;
    g_wB16[(size_t)((ic >> 5) * 2 + (oc >> 7)) * 4096 + fragoff(oc & 127, ic & 31)] =
        __float2half_rn(w1[idx]);
}

__global__ __launch_bounds__(256) void k_prep_x(const float* __restrict__ x) {
    size_t i = (size_t)blockIdx.x * 256 + threadIdx.x;   // over XVSZ/8
    size_t base = i * 8;
    int w0 = (int)(base & 127);
    const float* p = x + base;
    float4 a  = __ldg((const float4*)p);
    float4 b4 = __ldg((const float4*)(p + 4));
    float xm1 = (w0 > 0)   ? __ldg(p - 1) : 0.f;
    float xp8 = (w0 < 120) ? __ldg(p + 8) : 0.f;
    __half2* v0 = (__half2*)g_xv + i * 4;
    __half2* v1 = (__half2*)(g_xv + XVSZ) + i * 4;
    __half2* v2 = (__half2*)(g_xv + 2 * XVSZ) + i * 4;
    v1[0] = __floats2half2_rn(a.x, a.y);  v1[1] = __floats2half2_rn(a.z, a.w);
    v1[2] = __floats2half2_rn(b4.x, b4.y); v1[3] = __floats2half2_rn(b4.z, b4.w);
    v0[0] = __floats2half2_rn(xm1, a.x);  v0[1] = __floats2half2_rn(a.y, a.z);
    v0[2] = __floats2half2_rn(a.w, b4.x); v0[3] = __floats2half2_rn(b4.y, b4.z);
    v2[0] = __floats2half2_rn(a.y, a.z);  v2[1] = __floats2half2_rn(a.w, b4.x);
    v2[2] = __floats2half2_rn(b4.y, b4.z); v2[3] = __floats2half2_rn(b4.w, xp8);
}

__global__ __launch_bounds__(256) void k_zero_sh() {
    int idx = blockIdx.x * 256 + threadIdx.x;   // 524288
    if (idx >= 4 * 16 * 64 * 128) return;
    int grp = idx >> 17, r = idx & 131071;
    int b = r >> 13, r2 = r & 8191;
    int c = r2 >> 7, p = r2 & 127;
    int oc, h, w;
    if      (grp == 0) { oc = c;       h = p;   w = 0;   }
    else if (grp == 1) { oc = 64 + c;  h = 127; w = p;   }
    else if (grp == 2) { oc = 128 + c; h = p;   w = 127; }
    else               { oc = 192 + c; h = 0;   w = p;   }
    g_ysh[(((size_t)b * C2 + oc) << 14) + h * W_ + w] = __float2half_rn(0.f);
}

// --------------------------------------------------------- staging helpers --
__device__ __forceinline__ void cp_issue_A(uint Asm, const __half* src, int tid) {
    CP_A16(Asm + tid * 16, (const char*)src + tid * 16);
    CP_A16(Asm + 4096 + tid * 16, (const char*)src + 4096 + tid * 16);
}
// B: thread owns granule column g (=tid&15), rows kk0 and kk0+16 (kk0=tid>>4).
__device__ __forceinline__ void cp_issue_B(uint Bsm, const __half* vbase,
                                           int kk0, uint gxor, int hs, int wcol) {
    uint ok = ((uint)hs < 128u) ? 16u : 0u;
    int hsc = (hs < 0) ? 0 : (hs > 127 ? 127 : hs);
    const char* s = (const char*)(vbase + (size_t)kk0 * HW + hsc * W_ + wcol);
    uint d = Bsm + kk0 * 256 + gxor;
    CP_A16Z(d, s, ok);
    CP_A16Z(d + 16 * 256, s + (size_t)16 * HW * 2, ok);
}

// ----------------------------------------------------------------- MMA -----
// warp tile 32oc x 64px: wm=wrp>>1 (0..3), wn=wrp&1. mf 0..1, nf 0..7.
__device__ __forceinline__ void mma_chunk(uint Asm, uint Bsm, int wm, int wn,
                                          int lane, float acc[2][8][4]) {
    const int j = lane >> 3, r = lane & 7;
    const int jk = (j & 1) << 3, jn = j >> 1;
#pragma unroll
    for (int ks = 0; ks < 2; ++ks) {
        uint4 a[2];
#pragma unroll
        for (int mf = 0; mf < 2; ++mf) {
            uint ad = Asm + (((ks * 8 + wm * 2 + mf) * 32 + lane) << 4);
            asm volatile("ld.shared.v4.b32 {%0,%1,%2,%3}, [%4];"
                : "=r"(a[mf].x), "=r"(a[mf].y), "=r"(a[mf].z), "=r"(a[mf].w) : "r"(ad));
        }
        uint bf[8][2];
#pragma unroll
        for (int p = 0; p < 4; ++p) {
            int krow = ks * 16 + jk + r;
            int oct  = wn * 8 + 2 * p + jn;
            uint ad = Bsm + krow * 256 + ((uint)(oct ^ (krow & 7)) << 4);
            uint d0, d1, d2, d3;
            asm volatile("ldmatrix.sync.aligned.m8n8.x4.trans.shared.b16 "
                "{%0,%1,%2,%3}, [%4];"
                : "=r"(d0), "=r"(d1), "=r"(d2), "=r"(d3) : "r"(ad));
            bf[2 * p][0] = d0; bf[2 * p][1] = d1;
            bf[2 * p + 1][0] = d2; bf[2 * p + 1][1] = d3;
        }
#pragma unroll
        for (int mf = 0; mf < 2; ++mf)
#pragma unroll
            for (int nf = 0; nf < 8; ++nf)
                MMA16(acc[mf][nf], a[mf], bf[nf][0], bf[nf][1]);
    }
}

// ------------------------------------------------------ conv3x3 + BN + SiLU
__global__ __launch_bounds__(NTHR, 2) void k_conv3(
    const float* __restrict__ gamma, const float* __restrict__ beta,
    const float* __restrict__ mean,  const float* __restrict__ var)
{
    extern __shared__ __align__(16) char dsm[];
    const uint smb = smem_u32(dsm);

    const int tid = threadIdx.x;
    const int wrp = tid >> 5, lane = tid & 31;
    const int wm = wrp >> 1, wn = wrp & 1;
    const int kk0 = tid >> 4, g = tid & 15;
    const int wcol = g * 8;
    const uint gxor = ((uint)(g ^ (kk0 & 7))) << 4;
    const int h0  = blockIdx.x;
    const int ocg = blockIdx.y, oc0 = ocg * 128;
    const int b   = blockIdx.z;

    float acc[2][8][4];
#pragma unroll
    for (int i = 0; i < 2; ++i)
#pragma unroll
        for (int jj = 0; jj < 8; ++jj)
#pragma unroll
            for (int q = 0; q < 4; ++q) acc[i][jj][q] = 0.0f;

    const size_t bofs = (size_t)b * C1 * HW;
    // one sub-chunk issue (K=32)
#define SUB_CONV(nit, base) do { \
        int kc_ = (nit) / 9, tap_ = (nit) - 9 * kc_; \
        int ky_ = tap_ / 3, kx_ = tap_ - 3 * ky_; \
        cp_issue_A((base), g_wA16 + (size_t)((nit) * 2 + ocg) * 4096, tid); \
        const __half* vb_ = g_xv + (size_t)kx_ * XVSZ + bofs + (size_t)kc_ * 32 * HW; \
        cp_issue_B((base) + A_BYTES, vb_, kk0, gxor, h0 + ky_ - 1, wcol); \
    } while (0)
    // one stage = 2 sub-chunks + single commit
#define ISSUE_CONV(st, s) do { \
        SUB_CONV(2 * (st),     smb + (s) * STAGE); \
        SUB_CONV(2 * (st) + 1, smb + (s) * STAGE + CHUNK); \
        CP_COMMIT(); \
    } while (0)

    ISSUE_CONV(0, 0);
    ISSUE_CONV(1, 1);

#pragma unroll 1
    for (int st = 0; st < 18; ++st) {
        if (st + 2 < 18) CP_WAIT1(); else CP_WAIT0();
        __syncthreads();
        if (st + 2 < 18) {
            int s = (st + 2) % NSTG;
            ISSUE_CONV(st + 2, s);
        }
        const uint sb = smb + (st % NSTG) * STAGE;
        mma_chunk(sb,         sb + A_BYTES,         wm, wn, lane, acc);
        mma_chunk(sb + CHUNK, sb + CHUNK + A_BYTES, wm, wn, lane, acc);
    }
#undef ISSUE_CONV
#undef SUB_CONV

    // epilogue: BN + SiLU -> g_yi (plain) + g_ysh (shifted by group)
    const int grp = ((oc0 + wm * 32) >> 6) & 3;   // warp-uniform
    const int h = h0;
#pragma unroll
    for (int mf = 0; mf < 2; ++mf) {
        const int oc_a = oc0 + wm * 32 + mf * 16 + (lane >> 2);
        const int oc_b = oc_a + 8;
        const float inva = __ldg(&gamma[oc_a]) * rsqrtf(__ldg(&var[oc_a]) + EPSBN);
        const float bba  = __ldg(&beta[oc_a]) - __ldg(&mean[oc_a]) * inva;
        const float invb = __ldg(&gamma[oc_b]) * rsqrtf(__ldg(&var[oc_b]) + EPSBN);
        const float bbb  = __ldg(&beta[oc_b]) - __ldg(&mean[oc_b]) * invb;
        const size_t ra = ((size_t)b * C2 + oc_a) * HW;
        const size_t rb = ((size_t)b * C2 + oc_b) * HW;
#pragma unroll
        for (int nf = 0; nf < 8; ++nf) {
            const int w = wn * 64 + nf * 8 + (lane & 3) * 2;
            const int off = h * W_ + w;
            float2 u, v;
            u.x = silu_f(acc[mf][nf][0] * inva + bba);
            u.y = silu_f(acc[mf][nf][1] * inva + bba);
            v.x = silu_f(acc[mf][nf][2] * invb + bbb);
            v.y = silu_f(acc[mf][nf][3] * invb + bbb);
            __half2 uh = __floats2half2_rn(u.x, u.y);
            __half2 vh = __floats2half2_rn(v.x, v.y);
            *(__half2*)(g_yi + ra + off) = uh;
            *(__half2*)(g_yi + rb + off) = vh;
            if (grp == 0) {            // dest (h, w+1)
                g_ysh[ra + off + 1] = __low2half(uh);
                g_ysh[rb + off + 1] = __low2half(vh);
                if (w < 126) {
                    g_ysh[ra + off + 2] = __high2half(uh);
                    g_ysh[rb + off + 2] = __high2half(vh);
                }
            } else if (grp == 1) {     // dest (h-1, w)
                if (h > 0) {
                    *(__half2*)(g_ysh + ra + off - W_) = uh;
                    *(__half2*)(g_ysh + rb + off - W_) = vh;
                }
            } else if (grp == 2) {     // dest (h, w-1)
                if (w > 0) {
                    g_ysh[ra + off - 1] = __low2half(uh);
                    g_ysh[rb + off - 1] = __low2half(vh);
                }
                g_ysh[ra + off] = __high2half(uh);
                g_ysh[rb + off] = __high2half(vh);
            } else {                   // dest (h+1, w)
                if (h < 127) {
                    *(__half2*)(g_ysh + ra + off + W_) = uh;
                    *(__half2*)(g_ysh + rb + off + W_) = vh;
                }
            }
        }
    }
}

// --------------------------- conv1x1(shifted y) + bias + BN + id + SiLU ----
__global__ __launch_bounds__(NTHR, 2) void k_pw(
    const float* __restrict__ b1,
    const float* __restrict__ gamma, const float* __restrict__ beta,
    const float* __restrict__ mean,  const float* __restrict__ var,
    float* __restrict__ out)
{
    extern __shared__ __align__(16) char dsm[];
    const uint smb = smem_u32(dsm);

    const int tid = threadIdx.x;
    const int wrp = tid >> 5, lane = tid & 31;
    const int wm = wrp >> 1, wn = wrp & 1;
    const int kk0 = tid >> 4, g = tid & 15;
    const int wcol = g * 8;
    const uint gxor = ((uint)(g ^ (kk0 & 7))) << 4;
    const int h0  = blockIdx.x;
    const int ocg = blockIdx.y, oc0 = ocg * 128;
    const int b   = blockIdx.z;

    float acc[2][8][4];
#pragma unroll
    for (int i = 0; i < 2; ++i)
#pragma unroll
        for (int jj = 0; jj < 8; ++jj)
#pragma unroll
            for (int q = 0; q < 4; ++q) acc[i][jj][q] = 0.0f;

    const size_t bofs = (size_t)b * C2 * HW;
#define SUB_PW(nit, base) do { \
        cp_issue_A((base), g_wB16 + (size_t)((nit) * 2 + ocg) * 4096, tid); \
        const __half* vb_ = g_ysh + bofs + (size_t)(nit) * 32 * HW; \
        cp_issue_B((base) + A_BYTES, vb_, kk0, gxor, h0, wcol); \
    } while (0)
#define ISSUE_PW(st, s) do { \
        SUB_PW(2 * (st),     smb + (s) * STAGE); \
        SUB_PW(2 * (st) + 1, smb + (s) * STAGE + CHUNK); \
        CP_COMMIT(); \
    } while (0)

    ISSUE_PW(0, 0);
    ISSUE_PW(1, 1);

#pragma unroll 1
    for (int st = 0; st < 4; ++st) {
        if (st + 2 < 4) CP_WAIT1(); else CP_WAIT0();
        __syncthreads();
        if (st + 2 < 4) {
            int s = (st + 2) % NSTG;
            ISSUE_PW(st + 2, s);
        }
        const uint sb = smb + (st % NSTG) * STAGE;
        mma_chunk(sb,         sb + A_BYTES,         wm, wn, lane, acc);
        mma_chunk(sb + CHUNK, sb + CHUNK + A_BYTES, wm, wn, lane, acc);
    }
#undef ISSUE_PW
#undef SUB_PW

    // epilogue: +bias, BN, +identity(fp16), SiLU -> out (fp32)
    const int h = h0;
#pragma unroll
    for (int mf = 0; mf < 2; ++mf) {
        const int oc_a = oc0 + wm * 32 + mf * 16 + (lane >> 2);
        const int oc_b = oc_a + 8;
        const float inva = __ldg(&gamma[oc_a]) * rsqrtf(__ldg(&var[oc_a]) + EPSBN);
        const float bba  = __ldg(&beta[oc_a]) - __ldg(&mean[oc_a]) * inva;
        const float bsa  = __ldg(&b1[oc_a]);
        const float invb = __ldg(&gamma[oc_b]) * rsqrtf(__ldg(&var[oc_b]) + EPSBN);
        const float bbb  = __ldg(&beta[oc_b]) - __ldg(&mean[oc_b]) * invb;
        const float bsb  = __ldg(&b1[oc_b]);
        const size_t ra = ((size_t)b * C2 + oc_a) * HW;
        const size_t rb = ((size_t)b * C2 + oc_b) * HW;
#pragma unroll
        for (int nf = 0; nf < 8; ++nf) {
            const int w = wn * 64 + nf * 8 + (lane & 3) * 2;
            const int off = h * W_ + w;
            float2 ida = __half22float2(*(const __half2*)(g_yi + ra + off));
            float2 idb = __half22float2(*(const __half2*)(g_yi + rb + off));
            float2 u, v; float z;
            z = (acc[mf][nf][0] + bsa) * inva + bba + ida.x; u.x = silu_f(z);
            z = (acc[mf][nf][1] + bsa) * inva + bba + ida.y; u.y = silu_f(z);
            z = (acc[mf][nf][2] + bsb) * invb + bbb + idb.x; v.x = silu_f(z);
            z = (acc[mf][nf][3] + bsb) * invb + bbb + idb.y; v.y = silu_f(z);
            *(float2*)(out + ra + off) = u;
            *(float2*)(out + rb + off) = v;
        }
    }
}

// ---------------------------------------------------------------------------
extern "C" void kernel_launch(void* const* d_in, const int* in_sizes, int n_in,
                              void* d_out, int out_size)
{
    const float* x     = (const float*)d_in[0];
    const float* wconv = (const float*)d_in[1];
    const float* w1    = (const float*)d_in[2];
    const float* b1    = (const float*)d_in[3];
    const float* gamma = (const float*)d_in[4];
    const float* beta  = (const float*)d_in[5];
    const float* mean  = (const float*)d_in[6];
    const float* var   = (const float*)d_in[7];
    float* out = (float*)d_out;

    static bool attr_done = false;
    if (!attr_done) {
        cudaFuncSetAttribute(k_conv3, cudaFuncAttributeMaxDynamicSharedMemorySize, DSMEM_BYTES);
        cudaFuncSetAttribute(k_pw,    cudaFuncAttributeMaxDynamicSharedMemorySize, DSMEM_BYTES);
        attr_done = true;
    }

    k_repack_conv<<<(C2 * C1 * 9 + 255) / 256, 256>>>(wconv);
    k_repack_pw  <<<(C2 * C2 + 255) / 256, 256>>>(w1);
    k_prep_x     <<<(int)(XVSZ / 8 / 256), 256>>>(x);
    k_zero_sh    <<<(4 * 16 * 64 * 128 + 255) / 256, 256>>>();

    dim3 grid(H_, 2, B_);   // 128 rows x 2 oc-halves x 16 batch = 4096 CTAs
    k_conv3<<<grid, NTHR, DSMEM_BYTES>>>(gamma, beta, mean, var);
    k_pw   <<<grid, NTHR, DSMEM_BYTES>>>(b1, gamma, beta, mean, var, out);
}